// round 2
// baseline (speedup 1.0000x reference)
#include <cuda_runtime.h>
#include <cuda_bf16.h>

// ---------------------------------------------------------------------------
// Problem constants
// ---------------------------------------------------------------------------
#define B_    128
#define S_    256
#define L_    200
#define D_    768
#define POSD  50
#define FEAT  818     // POSD + D
#define REDUC 400
#define HID   150
#define PROJN 600     // 4*HID
#define TAGS  5
#define POL   4
#define M_    25600   // B_*L_

// ---------------------------------------------------------------------------
// Scratch (static device allocations; no cudaMalloc allowed)
// ---------------------------------------------------------------------------
__device__ float g_h[M_ * FEAT];        // [25600, 818]
__device__ float g_reduc[M_ * REDUC];   // [25600, 400]
__device__ float g_proj[M_ * PROJN];    // [25600, 600] = ap_rep|op_rep|ap_node|op_node
__device__ float g_affine[M_ * PROJN];  // [25600, 600] -> per batch [800,150]
__device__ float g_Wproj[PROJN * REDUC];
__device__ float g_bproj[PROJN];
__device__ float g_bbi[PROJN];

// ---------------------------------------------------------------------------
// Prep: concat the 4 HID projection weights/biases; extract biaffine bias col
// ---------------------------------------------------------------------------
__global__ void prep_kernel(const float* __restrict__ Wap, const float* __restrict__ bap,
                            const float* __restrict__ Wop, const float* __restrict__ bop,
                            const float* __restrict__ Wap2, const float* __restrict__ bap2,
                            const float* __restrict__ Wop2, const float* __restrict__ bop2,
                            const float* __restrict__ Wbi)
{
    int i = blockIdx.x * blockDim.x + threadIdx.x;
    if (i < PROJN * REDUC) {
        int n = i / REDUC, k = i % REDUC;
        const float* src = (n < 150) ? Wap : (n < 300) ? Wop : (n < 450) ? Wap2 : Wop2;
        g_Wproj[i] = src[(n % 150) * REDUC + k];
    }
    if (i < PROJN) {
        const float* sb = (i < 150) ? bap : (i < 300) ? bop : (i < 450) ? bap2 : bop2;
        g_bproj[i] = sb[i % 150];
        g_bbi[i]   = Wbi[i * 151 + 150];   // bias column of [ap_node, 1] input
    }
}

// ---------------------------------------------------------------------------
// Pool subwords (spans of 1..3) + gather POS embedding -> h[m, 818]
// ---------------------------------------------------------------------------
__global__ void pool_embed_kernel(const float* __restrict__ bert,
                                  const int* __restrict__ positions,
                                  const int* __restrict__ postag,
                                  const float* __restrict__ embed)
{
    int m = blockIdx.x;                 // word index 0..25599
    int b = m / L_;
    __shared__ int s_start, s_end, s_tag;
    if (threadIdx.x == 0) {
        s_start = positions[m * 2 + 0];
        s_end   = positions[m * 2 + 1];
        s_tag   = postag[m];
    }
    __syncthreads();
    const int start = s_start, end = s_end, tag = s_tag;
    const float inv = 1.0f / (float)(end - start + 1);
    const float* bb = bert + (long)b * S_ * D_;
    float* hrow = g_h + (long)m * FEAT;
    for (int f = threadIdx.x; f < FEAT; f += blockDim.x) {
        float v;
        if (f < POSD) {
            v = embed[tag * POSD + f];
        } else {
            int d = f - POSD;
            float s = 0.0f;
            for (int si = start; si <= end; si++) s += bb[(long)si * D_ + d];
            v = s * inv;
        }
        hrow[f] = v;
    }
}

// ---------------------------------------------------------------------------
// Generic tiled SGEMM:  C[m,n] = sum_k A[m,k] * W[n,k] (+bias[n]) (relu?)
// A: [M, lda] row-major view, W: [N, ldw], C: [M, ldc]; optional batch strides.
// 64x64 tile, BK=16, 256 threads, 4x4 per thread.
// ---------------------------------------------------------------------------
#define BM 64
#define BN 64
#define BK 16
__global__ __launch_bounds__(256)
void gemm_nt(const float* __restrict__ A, int lda, long strideA,
             const float* __restrict__ W, int ldw, long strideW,
             const float* __restrict__ bias,
             float* __restrict__ C, int ldc, long strideC,
             int M, int N, int K, int relu)
{
    const int bz = blockIdx.z;
    A += (long)bz * strideA;
    W += (long)bz * strideW;
    C += (long)bz * strideC;

    const int m0 = blockIdx.y * BM;
    const int n0 = blockIdx.x * BN;

    __shared__ float As[BK][BM];
    __shared__ float Ws[BK][BN];

    const int tid = threadIdx.x;
    const int tr = tid / 16;   // 0..15
    const int tc = tid % 16;   // 0..15

    float acc[4][4] = {};

    for (int k0 = 0; k0 < K; k0 += BK) {
#pragma unroll
        for (int j = 0; j < 4; j++) {
            int i  = tid + j * 256;        // 0..1023
            int mm = i / BK;               // 0..63
            int kk = i % BK;               // 0..15
            int gm = m0 + mm, gk = k0 + kk;
            As[kk][mm] = (gm < M && gk < K) ? A[(long)gm * lda + gk] : 0.0f;
            int gn = n0 + mm;
            Ws[kk][mm] = (gn < N && gk < K) ? W[(long)gn * ldw + gk] : 0.0f;
        }
        __syncthreads();
#pragma unroll
        for (int kk = 0; kk < BK; kk++) {
            float4 av = *reinterpret_cast<const float4*>(&As[kk][tr * 4]);
            float4 wv = *reinterpret_cast<const float4*>(&Ws[kk][tc * 4]);
            float a[4] = {av.x, av.y, av.z, av.w};
            float w[4] = {wv.x, wv.y, wv.z, wv.w};
#pragma unroll
            for (int i = 0; i < 4; i++)
#pragma unroll
                for (int j = 0; j < 4; j++)
                    acc[i][j] += a[i] * w[j];
        }
        __syncthreads();
    }

#pragma unroll
    for (int i = 0; i < 4; i++) {
        int gm = m0 + tr * 4 + i;
        if (gm >= M) continue;
#pragma unroll
        for (int j = 0; j < 4; j++) {
            int gn = n0 + tc * 4 + j;
            if (gn >= N) continue;
            float v = acc[i][j] + (bias ? bias[gn] : 0.0f);
            if (relu) v = fmaxf(v, 0.0f);
            C[(long)gm * ldc + gn] = v;
        }
    }
}

// ---------------------------------------------------------------------------
// Tag heads: ap_out / op_out  (N=5 each, K=150)  -> start of d_out
// ---------------------------------------------------------------------------
__global__ void tag_kernel(const float* __restrict__ Wap, const float* __restrict__ bap,
                           const float* __restrict__ Wop, const float* __restrict__ bop,
                           float* __restrict__ out)
{
    int i = blockIdx.x * blockDim.x + threadIdx.x;   // 25600*10
    if (i >= M_ * 2 * TAGS) return;
    int m = i / (2 * TAGS);
    int r = i % (2 * TAGS);
    int t = r % TAGS;
    bool is_op = (r >= TAGS);
    const float* a = g_proj + (long)m * PROJN + (is_op ? 150 : 0);
    const float* w = (is_op ? Wop : Wap) + t * HID;
    float s = (is_op ? bop : bap)[t];
#pragma unroll 5
    for (int k = 0; k < HID; k++) s += a[k] * w[k];
    out[(is_op ? (long)M_ * TAGS : 0l) + (long)m * TAGS + t] = s;
}

// ---------------------------------------------------------------------------
// kernel_launch
// ---------------------------------------------------------------------------
static float* sym_addr(const void* symbol) {
    void* p = nullptr;
    cudaGetSymbolAddress(&p, symbol);
    return (float*)p;
}

extern "C" void kernel_launch(void* const* d_in, const int* in_sizes, int n_in,
                              void* d_out, int out_size)
{
    const float* bert      = (const float*)d_in[0];
    const int*   positions = (const int*)  d_in[1];
    const int*   postag    = (const int*)  d_in[2];
    const float* embed     = (const float*)d_in[3];
    const float* W_reduc   = (const float*)d_in[4];
    const float* b_reduc   = (const float*)d_in[5];
    const float* W_ap      = (const float*)d_in[6];
    const float* b_ap      = (const float*)d_in[7];
    const float* W_op      = (const float*)d_in[8];
    const float* b_op      = (const float*)d_in[9];
    const float* W_ap2     = (const float*)d_in[10];
    const float* b_ap2     = (const float*)d_in[11];
    const float* W_op2     = (const float*)d_in[12];
    const float* b_op2     = (const float*)d_in[13];
    const float* W_aptag   = (const float*)d_in[14];
    const float* b_aptag   = (const float*)d_in[15];
    const float* W_optag   = (const float*)d_in[16];
    const float* b_optag   = (const float*)d_in[17];
    const float* W_bi      = (const float*)d_in[18];
    float* out = (float*)d_out;

    float* p_h      = sym_addr(g_h);
    float* p_reduc  = sym_addr(g_reduc);
    float* p_proj   = sym_addr(g_proj);
    float* p_affine = sym_addr(g_affine);
    float* p_Wproj  = sym_addr(g_Wproj);
    float* p_bproj  = sym_addr(g_bproj);
    float* p_bbi    = sym_addr(g_bbi);

    // 1. prep concat weights (tiny)
    prep_kernel<<<(PROJN * REDUC + 255) / 256, 256>>>(
        W_ap, b_ap, W_op, b_op, W_ap2, b_ap2, W_op2, b_op2, W_bi);

    // 2. pooling + embedding -> h [25600, 818]
    pool_embed_kernel<<<M_, 256>>>(bert, positions, postag, embed);

    // 3. reduc = h @ W_reduc^T + b   [25600, 400]
    gemm_nt<<<dim3((REDUC + BN - 1) / BN, M_ / BM, 1), 256>>>(
        p_h, FEAT, 0, W_reduc, FEAT, 0, b_reduc,
        p_reduc, REDUC, 0, M_, REDUC, FEAT, 0);

    // 4. fused 4x projection + relu -> proj [25600, 600]
    gemm_nt<<<dim3((PROJN + BN - 1) / BN, M_ / BM, 1), 256>>>(
        p_reduc, REDUC, 0, p_Wproj, REDUC, 0, p_bproj,
        p_proj, PROJN, 0, M_, PROJN, REDUC, 1);

    // 5. affine = [ap_node,1] @ W_bi^T  -> [25600, 600] (== per-batch [800,150])
    gemm_nt<<<dim3((PROJN + BN - 1) / BN, M_ / BM, 1), 256>>>(
        p_proj + 300, PROJN, 0, W_bi, 151, 0, p_bbi,
        p_affine, PROJN, 0, M_, PROJN, HID, 0);

    // 6. tag heads -> out[0 : 256000]
    tag_kernel<<<(M_ * 10 + 255) / 256, 256>>>(W_aptag, b_aptag, W_optag, b_optag, out);

    // 7. triplet: per batch  C[l2, l1*4+p] = op_node[l2,:] . affine[l1*4+p,:]
    //    -> out[256000 + b*160000 + l2*800 + n]
    gemm_nt<<<dim3((800 + BN - 1) / BN, (L_ + BM - 1) / BM, B_), 256>>>(
        p_proj + 450, PROJN, (long)L_ * PROJN,
        p_affine, HID, (long)L_ * PROJN,
        nullptr,
        out + 2l * M_ * TAGS, 800, (long)L_ * 800,
        L_, 800, HID, 0);
}

// round 3
// speedup vs baseline: 1.7585x; 1.7585x over previous
#include <cuda_runtime.h>
#include <cuda_bf16.h>

// ---------------------------------------------------------------------------
// Problem constants
// ---------------------------------------------------------------------------
#define B_    128
#define S_    256
#define L_    200
#define D_    768
#define POSD  50
#define FEAT  818     // POSD + D
#define REDUC 400
#define HID   150
#define PROJN 600     // 4*HID
#define TAGS  5
#define POL   4
#define M_    25600   // B_*L_

// ---------------------------------------------------------------------------
// Scratch (static device allocations; no cudaMalloc allowed)
// ---------------------------------------------------------------------------
__device__ float g_h[M_ * FEAT];        // [25600, 818]
__device__ float g_reduc[M_ * REDUC];   // [25600, 400]
__device__ float g_proj[M_ * PROJN];    // [25600, 600] = ap_rep|op_rep|ap_node|op_node
__device__ float g_affine[M_ * PROJN];  // [25600, 600] -> per batch [800,150]
__device__ float g_Wproj[PROJN * REDUC];
__device__ float g_bproj[PROJN];
__device__ float g_bbi[PROJN];

// ---------------------------------------------------------------------------
// Prep: concat the 4 HID projection weights/biases; extract biaffine bias col
// ---------------------------------------------------------------------------
__global__ void prep_kernel(const float* __restrict__ Wap, const float* __restrict__ bap,
                            const float* __restrict__ Wop, const float* __restrict__ bop,
                            const float* __restrict__ Wap2, const float* __restrict__ bap2,
                            const float* __restrict__ Wop2, const float* __restrict__ bop2,
                            const float* __restrict__ Wbi)
{
    int i = blockIdx.x * blockDim.x + threadIdx.x;
    if (i < PROJN * REDUC) {
        int n = i / REDUC, k = i % REDUC;
        const float* src = (n < 150) ? Wap : (n < 300) ? Wop : (n < 450) ? Wap2 : Wop2;
        g_Wproj[i] = src[(n % 150) * REDUC + k];
    }
    if (i < PROJN) {
        const float* sb = (i < 150) ? bap : (i < 300) ? bop : (i < 450) ? bap2 : bop2;
        g_bproj[i] = sb[i % 150];
        g_bbi[i]   = Wbi[i * 151 + 150];   // bias column of [ap_node, 1] input
    }
}

// ---------------------------------------------------------------------------
// Pool subwords (spans of 1..3) + gather POS embedding -> h[m, 818]
// ---------------------------------------------------------------------------
__global__ void pool_embed_kernel(const float* __restrict__ bert,
                                  const int* __restrict__ positions,
                                  const int* __restrict__ postag,
                                  const float* __restrict__ embed)
{
    int m = blockIdx.x;                 // word index 0..25599
    int b = m / L_;
    __shared__ int s_start, s_end, s_tag;
    if (threadIdx.x == 0) {
        s_start = positions[m * 2 + 0];
        s_end   = positions[m * 2 + 1];
        s_tag   = postag[m];
    }
    __syncthreads();
    const int start = s_start, end = s_end, tag = s_tag;
    const float inv = 1.0f / (float)(end - start + 1);
    const float* bb = bert + (long)b * S_ * D_;
    float* hrow = g_h + (long)m * FEAT;
    for (int f = threadIdx.x; f < FEAT; f += blockDim.x) {
        float v;
        if (f < POSD) {
            v = embed[tag * POSD + f];
        } else {
            int d = f - POSD;
            float s = 0.0f;
            for (int si = start; si <= end; si++) s += bb[(long)si * D_ + d];
            v = s * inv;
        }
        hrow[f] = v;
    }
}

// ---------------------------------------------------------------------------
// High-intensity tiled SGEMM:  C[m,n] = sum_k A[m,k]*W[n,k] (+bias) (relu?)
// BMxBN tile, BK=8, 256 threads, TMxTN register microtile, double-buffered
// smem, guarded scalar global loads (handles any K/M/N).
// (BM/TM)*(BN/TN) must equal 256; TM,TN even.
// ---------------------------------------------------------------------------
template<int BM, int BN, int TM, int TN>
__global__ __launch_bounds__(256)
void gemm_big(const float* __restrict__ A, int lda, long sA,
              const float* __restrict__ W, int ldw, long sW,
              const float* __restrict__ bias,
              float* __restrict__ C, int ldc, long sC,
              int M, int N, int K, int relu)
{
    constexpr int BK  = 8;
    constexpr int EA  = BM * BK / 256;   // A elems per thread per tile
    constexpr int EW  = BN * BK / 256;   // W elems per thread per tile
    constexpr int HTM = TM / 2;
    constexpr int HTN = TN / 2;

    const int bz = blockIdx.z;
    A += (long)bz * sA;
    W += (long)bz * sW;
    C += (long)bz * sC;

    const int m0 = blockIdx.y * BM;
    const int n0 = blockIdx.x * BN;
    const int tid = threadIdx.x;
    const int tx = tid % 16;     // BN/TN == 16 for both variants
    const int ty = tid / 16;     // BM/TM == 16

    __shared__ float As[2][BK][BM];
    __shared__ float Ws[2][BK][BN];

    float acc[TM][TN] = {};
    float pa[EA], pw[EW];

    const int numT = (K + BK - 1) / BK;

    // ---- prologue: load tile 0 straight to smem ----
#pragma unroll
    for (int i = 0; i < EA; i++) {
        int idx = tid * EA + i;                 // k-contiguous per thread
        int r = idx / BK, c = idx % BK;
        int gm = m0 + r, gk = c;
        As[0][c][r] = (gm < M && gk < K) ? A[(long)gm * lda + gk] : 0.0f;
    }
#pragma unroll
    for (int i = 0; i < EW; i++) {
        int idx = tid * EW + i;
        int r = idx / BK, c = idx % BK;
        int gn = n0 + r, gk = c;
        Ws[0][c][r] = (gn < N && gk < K) ? W[(long)gn * ldw + gk] : 0.0f;
    }
    __syncthreads();

    int cur = 0;
    for (int t = 0; t < numT; t++) {
        // ---- prefetch tile t+1 into registers (overlaps compute) ----
        const bool more = (t + 1 < numT);
        if (more) {
            const int kbase = (t + 1) * BK;
#pragma unroll
            for (int i = 0; i < EA; i++) {
                int idx = tid * EA + i;
                int r = idx / BK, c = idx % BK;
                int gm = m0 + r, gk = kbase + c;
                pa[i] = (gm < M && gk < K) ? A[(long)gm * lda + gk] : 0.0f;
            }
#pragma unroll
            for (int i = 0; i < EW; i++) {
                int idx = tid * EW + i;
                int r = idx / BK, c = idx % BK;
                int gn = n0 + r, gk = kbase + c;
                pw[i] = (gn < N && gk < K) ? W[(long)gn * ldw + gk] : 0.0f;
            }
        }

        // ---- compute on buffer `cur` ----
#pragma unroll
        for (int kk = 0; kk < BK; kk++) {
            float a[TM], w[TN];
            if constexpr (HTM == 4) {
                float4 lo = *reinterpret_cast<const float4*>(&As[cur][kk][ty * 4]);
                float4 hi = *reinterpret_cast<const float4*>(&As[cur][kk][BM / 2 + ty * 4]);
                a[0] = lo.x; a[1] = lo.y; a[2] = lo.z; a[3] = lo.w;
                a[4] = hi.x; a[5] = hi.y; a[6] = hi.z; a[7] = hi.w;
            } else {
                float2 lo = *reinterpret_cast<const float2*>(&As[cur][kk][ty * 2]);
                float2 hi = *reinterpret_cast<const float2*>(&As[cur][kk][BM / 2 + ty * 2]);
                a[0] = lo.x; a[1] = lo.y; a[2] = hi.x; a[3] = hi.y;
            }
            if constexpr (HTN == 4) {
                float4 lo = *reinterpret_cast<const float4*>(&Ws[cur][kk][tx * 4]);
                float4 hi = *reinterpret_cast<const float4*>(&Ws[cur][kk][BN / 2 + tx * 4]);
                w[0] = lo.x; w[1] = lo.y; w[2] = lo.z; w[3] = lo.w;
                w[4] = hi.x; w[5] = hi.y; w[6] = hi.z; w[7] = hi.w;
            } else {
                float2 lo = *reinterpret_cast<const float2*>(&Ws[cur][kk][tx * 2]);
                float2 hi = *reinterpret_cast<const float2*>(&Ws[cur][kk][BN / 2 + tx * 2]);
                w[0] = lo.x; w[1] = lo.y; w[2] = hi.x; w[3] = hi.y;
            }
#pragma unroll
            for (int i = 0; i < TM; i++)
#pragma unroll
                for (int j = 0; j < TN; j++)
                    acc[i][j] = fmaf(a[i], w[j], acc[i][j]);
        }

        // ---- commit prefetch into the other buffer ----
        if (more) {
            int nxt = cur ^ 1;
#pragma unroll
            for (int i = 0; i < EA; i++) {
                int idx = tid * EA + i;
                As[nxt][idx % BK][idx / BK] = pa[i];
            }
#pragma unroll
            for (int i = 0; i < EW; i++) {
                int idx = tid * EW + i;
                Ws[nxt][idx % BK][idx / BK] = pw[i];
            }
            __syncthreads();
            cur = nxt;
        }
    }

    // ---- epilogue ----
#pragma unroll
    for (int i = 0; i < TM; i++) {
        int gm = m0 + ((i < HTM) ? (ty * HTM + i) : (BM / 2 + ty * HTM + (i - HTM)));
        if (gm >= M) continue;
#pragma unroll
        for (int j = 0; j < TN; j++) {
            int gn = n0 + ((j < HTN) ? (tx * HTN + j) : (BN / 2 + tx * HTN + (j - HTN)));
            if (gn >= N) continue;
            float v = acc[i][j] + (bias ? bias[gn] : 0.0f);
            if (relu) v = fmaxf(v, 0.0f);
            C[(long)gm * ldc + gn] = v;
        }
    }
}

// ---------------------------------------------------------------------------
// Tag heads: ap_out / op_out  (N=5 each, K=150)  -> start of d_out
// ---------------------------------------------------------------------------
__global__ void tag_kernel(const float* __restrict__ Wap, const float* __restrict__ bap,
                           const float* __restrict__ Wop, const float* __restrict__ bop,
                           float* __restrict__ out)
{
    int i = blockIdx.x * blockDim.x + threadIdx.x;   // 25600*10
    if (i >= M_ * 2 * TAGS) return;
    int m = i / (2 * TAGS);
    int r = i % (2 * TAGS);
    int t = r % TAGS;
    bool is_op = (r >= TAGS);
    const float* a = g_proj + (long)m * PROJN + (is_op ? 150 : 0);
    const float* w = (is_op ? Wop : Wap) + t * HID;
    float s = (is_op ? bop : bap)[t];
#pragma unroll 5
    for (int k = 0; k < HID; k++) s += a[k] * w[k];
    out[(is_op ? (long)M_ * TAGS : 0l) + (long)m * TAGS + t] = s;
}

// ---------------------------------------------------------------------------
// kernel_launch
// ---------------------------------------------------------------------------
static float* sym_addr(const void* symbol) {
    void* p = nullptr;
    cudaGetSymbolAddress(&p, symbol);
    return (float*)p;
}

extern "C" void kernel_launch(void* const* d_in, const int* in_sizes, int n_in,
                              void* d_out, int out_size)
{
    const float* bert      = (const float*)d_in[0];
    const int*   positions = (const int*)  d_in[1];
    const int*   postag    = (const int*)  d_in[2];
    const float* embed     = (const float*)d_in[3];
    const float* W_reduc   = (const float*)d_in[4];
    const float* b_reduc   = (const float*)d_in[5];
    const float* W_ap      = (const float*)d_in[6];
    const float* b_ap      = (const float*)d_in[7];
    const float* W_op      = (const float*)d_in[8];
    const float* b_op      = (const float*)d_in[9];
    const float* W_ap2     = (const float*)d_in[10];
    const float* b_ap2     = (const float*)d_in[11];
    const float* W_op2     = (const float*)d_in[12];
    const float* b_op2     = (const float*)d_in[13];
    const float* W_aptag   = (const float*)d_in[14];
    const float* b_aptag   = (const float*)d_in[15];
    const float* W_optag   = (const float*)d_in[16];
    const float* b_optag   = (const float*)d_in[17];
    const float* W_bi      = (const float*)d_in[18];
    float* out = (float*)d_out;

    float* p_h      = sym_addr(g_h);
    float* p_reduc  = sym_addr(g_reduc);
    float* p_proj   = sym_addr(g_proj);
    float* p_affine = sym_addr(g_affine);
    float* p_Wproj  = sym_addr(g_Wproj);
    float* p_bproj  = sym_addr(g_bproj);
    float* p_bbi    = sym_addr(g_bbi);

    // 1. prep concat weights (tiny)
    prep_kernel<<<(PROJN * REDUC + 255) / 256, 256>>>(
        W_ap, b_ap, W_op, b_op, W_ap2, b_ap2, W_op2, b_op2, W_bi);

    // 2. pooling + embedding -> h [25600, 818]
    pool_embed_kernel<<<M_, 256>>>(bert, positions, postag, embed);

    // 3. reduc = h @ W_reduc^T + b   [25600, 400]   (128x64 tiles, N=400)
    gemm_big<128, 64, 8, 4><<<dim3((REDUC + 63) / 64, (M_ + 127) / 128, 1), 256>>>(
        p_h, FEAT, 0, W_reduc, FEAT, 0, b_reduc,
        p_reduc, REDUC, 0, M_, REDUC, FEAT, 0);

    // 4. fused 4x projection + relu -> proj [25600, 600]   (128x128)
    gemm_big<128, 128, 8, 8><<<dim3((PROJN + 127) / 128, (M_ + 127) / 128, 1), 256>>>(
        p_reduc, REDUC, 0, p_Wproj, REDUC, 0, p_bproj,
        p_proj, PROJN, 0, M_, PROJN, REDUC, 1);

    // 5. affine = [ap_node,1] @ W_bi^T -> [25600,600] (== per-batch [800,150])
    gemm_big<128, 128, 8, 8><<<dim3((PROJN + 127) / 128, (M_ + 127) / 128, 1), 256>>>(
        p_proj + 300, PROJN, 0, W_bi, 151, 0, p_bbi,
        p_affine, PROJN, 0, M_, PROJN, HID, 0);

    // 6. tag heads -> out[0 : 256000]
    tag_kernel<<<(M_ * 10 + 255) / 256, 256>>>(W_aptag, b_aptag, W_optag, b_optag, out);

    // 7. triplet: per batch  C[l2, l1*4+p] = op_node[l2,:] . affine[l1*4+p,:]
    //    -> out[256000 + b*160000 + l2*800 + n]   (128x64 tiles, M=200, N=800)
    gemm_big<128, 64, 8, 4><<<dim3((800 + 63) / 64, (L_ + 127) / 128, B_), 256>>>(
        p_proj + 450, PROJN, (long)L_ * PROJN,
        p_affine, HID, (long)L_ * PROJN,
        nullptr,
        out + 2l * M_ * TAGS, 800, (long)L_ * 800,
        L_, 800, HID, 0);
}

// round 6
// speedup vs baseline: 3.4468x; 1.9601x over previous
#include <cuda_runtime.h>
#include <cuda_bf16.h>
#include <cstdint>

// ---------------------------------------------------------------------------
// Problem constants
// ---------------------------------------------------------------------------
#define B_    128
#define S_    256
#define L_    200
#define D_    768
#define POSD  50
#define FEAT  818
#define REDUC 400
#define HID   150
#define PROJN 600
#define TAGS  5
#define POL   4
#define M_    25600

// K paddings (chunks of 64 bf16); buffers hold [hi(Kp) | lo(Kp)] per row
#define KP_H   832   // FEAT=818 -> T=13
#define KP_R   448   // REDUC=400 -> T=7
#define KP_N   192   // HID=150 -> T=3

// ---------------------------------------------------------------------------
// Scratch
// ---------------------------------------------------------------------------
__device__ __align__(128) __nv_bfloat16 g_hbf[(long)M_ * 2 * KP_H];
__device__ __align__(128) __nv_bfloat16 g_Wr_bf[(long)REDUC * 2 * KP_H];
__device__ float g_reduc[(long)M_ * REDUC];
__device__ __align__(128) __nv_bfloat16 g_reduc_bf[(long)M_ * 2 * KP_R];
__device__ float g_WprojF[PROJN * REDUC];
__device__ __align__(128) __nv_bfloat16 g_Wp_bf[(long)PROJN * 2 * KP_R];
__device__ float g_bproj[PROJN];
__device__ float g_bbi[PROJN];
__device__ float g_proj[(long)M_ * PROJN];
__device__ __align__(128) __nv_bfloat16 g_apn_bf[(long)M_ * 2 * KP_N];
__device__ __align__(128) __nv_bfloat16 g_opn_bf[(long)M_ * 2 * KP_N];
__device__ __align__(128) __nv_bfloat16 g_Wbi_bf[(long)PROJN * 2 * KP_N];
__device__ float g_affine[(long)M_ * PROJN];
__device__ __align__(128) __nv_bfloat16 g_aff_bf[(long)B_ * 800 * 2 * KP_N];

// ---------------------------------------------------------------------------
// PTX helpers (family-common only: cp.async / ldmatrix / mma.sync)
// ---------------------------------------------------------------------------
__device__ __forceinline__ uint32_t smem_u32(const void* p) {
    uint32_t a;
    asm("{ .reg .u64 t; cvta.to.shared.u64 t, %1; cvt.u32.u64 %0, t; }" : "=r"(a) : "l"(p));
    return a;
}
__device__ __forceinline__ void cp_async16(uint32_t dst, const void* src, int sz) {
    asm volatile("cp.async.cg.shared.global [%0], [%1], 16, %2;"
                 :: "r"(dst), "l"(src), "r"(sz) : "memory");
}
#define CP_COMMIT() asm volatile("cp.async.commit_group;" ::: "memory")
#define CP_WAIT(n)  asm volatile("cp.async.wait_group %0;" :: "n"(n) : "memory")

__device__ __forceinline__ uint32_t swz(uint32_t off) {
    return off ^ ((off >> 3) & 0x70);
}
__device__ __forceinline__ void ldsm_x4(uint32_t* r, uint32_t addr) {
    asm volatile("ldmatrix.sync.aligned.m8n8.x4.shared.b16 {%0,%1,%2,%3}, [%4];"
                 : "=r"(r[0]), "=r"(r[1]), "=r"(r[2]), "=r"(r[3]) : "r"(addr));
}
__device__ __forceinline__ void ldsm_x2(uint32_t* r, uint32_t addr) {
    asm volatile("ldmatrix.sync.aligned.m8n8.x2.shared.b16 {%0,%1}, [%2];"
                 : "=r"(r[0]), "=r"(r[1]) : "r"(addr));
}
__device__ __forceinline__ void mma_bf16(float* c, const uint32_t* a, const uint32_t* b) {
    asm volatile(
        "mma.sync.aligned.m16n8k16.row.col.f32.bf16.bf16.f32 "
        "{%0,%1,%2,%3}, {%4,%5,%6,%7}, {%8,%9}, {%0,%1,%2,%3};"
        : "+f"(c[0]), "+f"(c[1]), "+f"(c[2]), "+f"(c[3])
        : "r"(a[0]), "r"(a[1]), "r"(a[2]), "r"(a[3]), "r"(b[0]), "r"(b[1]));
}

// ---------------------------------------------------------------------------
// mma.sync split-bf16 GEMM:  C[m,n] = sum over 3 split terms of A''.B''^T
// A'': [rows, 2*Kp] = [hi|lo] bf16, B'' same. CTA tile 128x128, BK=64.
// 8 warps (2 M x 4 N), warp tile 64x32, double-buffered cp.async smem.
// ---------------------------------------------------------------------------
#define SMEM_BYTES 65536

__global__ __launch_bounds__(256, 2)
void gemm_mma(const __nv_bfloat16* __restrict__ A, int lda, long sA, int Mrows,
              const __nv_bfloat16* __restrict__ Bw, int ldb, long sB, int Nrows,
              const float* __restrict__ bias,
              float* __restrict__ C, int ldc, long sC,
              int T, int relu)
{
    extern __shared__ char smem[];
    const uint32_t sbase = smem_u32(smem);
    const int tid = threadIdx.x, wid = tid >> 5, lane = tid & 31;
    const int m0 = blockIdx.y * 128;
    const int n0 = blockIdx.x * 128;
    A  += (long)blockIdx.z * sA;
    Bw += (long)blockIdx.z * sB;
    C  += (long)blockIdx.z * sC;
    const int NT = 3 * T;

    const int wm = wid & 1;        // 0..1 : M quadrant (64 rows)
    const int wn = wid >> 1;       // 0..3 : N quadrant (32 cols)

    float acc[4][4][4];
#pragma unroll
    for (int i = 0; i < 4; i++)
#pragma unroll
        for (int j = 0; j < 4; j++)
#pragma unroll
            for (int k = 0; k < 4; k++) acc[i][j][k] = 0.0f;

    // stage loader: chunk t -> buffer (A 16KB, B 16KB)
    auto load_stage = [&](int t, int buf) {
        const int ka = (t < T) ? t : t - T;            // A: hi, hi, lo
        const int kb = (t < 2 * T) ? t : t - 2 * T;    // B: hi, lo, hi
        const uint32_t abase = sbase + (uint32_t)buf * 32768u;
        const uint32_t bbase = abase + 16384u;
#pragma unroll
        for (int i = 0; i < 4; i++) {
            int idx = i * 256 + tid;            // 0..1023
            int r = idx >> 3, c = idx & 7;
            int gm = m0 + r;
            int ok = (gm < Mrows);
            const char* src = (const char*)(A + (long)(ok ? gm : 0) * lda + (long)ka * 64) + c * 16;
            cp_async16(abase + swz((uint32_t)(r * 128 + c * 16)), src, ok ? 16 : 0);
        }
#pragma unroll
        for (int i = 0; i < 4; i++) {
            int idx = i * 256 + tid;
            int r = idx >> 3, c = idx & 7;
            int gn = n0 + r;
            int ok = (gn < Nrows);
            const char* src = (const char*)(Bw + (long)(ok ? gn : 0) * ldb + (long)kb * 64) + c * 16;
            cp_async16(bbase + swz((uint32_t)(r * 128 + c * 16)), src, ok ? 16 : 0);
        }
        CP_COMMIT();
    };

    load_stage(0, 0);

    for (int t = 0; t < NT; t++) {
        const int buf = t & 1;
        if (t + 1 < NT) {
            load_stage(t + 1, buf ^ 1);
            CP_WAIT(1);
        } else {
            CP_WAIT(0);
        }
        __syncthreads();

        const uint32_t abase = sbase + (uint32_t)buf * 32768u;
        const uint32_t bbase = abase + 16384u;
#pragma unroll
        for (int ks = 0; ks < 4; ks++) {
            uint32_t ra[4][4], rb[4][2];
#pragma unroll
            for (int mi = 0; mi < 4; mi++) {
                int row = wm * 64 + mi * 16 + (lane & 15);
                uint32_t off = (uint32_t)(row * 128 + ks * 32 + (lane >> 4) * 16);
                ldsm_x4(ra[mi], abase + swz(off));
            }
#pragma unroll
            for (int ni = 0; ni < 4; ni++) {
                int l16 = lane & 15;
                int row = wn * 32 + ni * 8 + (l16 & 7);
                uint32_t off = (uint32_t)(row * 128 + ks * 32 + ((l16 >> 3) & 1) * 16);
                ldsm_x2(rb[ni], bbase + swz(off));
            }
#pragma unroll
            for (int mi = 0; mi < 4; mi++)
#pragma unroll
                for (int ni = 0; ni < 4; ni++)
                    mma_bf16(acc[mi][ni], ra[mi], rb[ni]);
        }
        __syncthreads();
    }

    // epilogue: c0:(r,c) c1:(r,c+1) c2:(r+8,c) c3:(r+8,c+1)
#pragma unroll
    for (int mi = 0; mi < 4; mi++) {
        int rb0 = m0 + wm * 64 + mi * 16 + (lane >> 2);
#pragma unroll
        for (int ni = 0; ni < 4; ni++) {
            int cb = n0 + wn * 32 + ni * 8 + (lane & 3) * 2;
#pragma unroll
            for (int half = 0; half < 2; half++) {
                int gm = rb0 + half * 8;
                if (gm >= Mrows) continue;
                float* crow = C + (long)gm * ldc;
#pragma unroll
                for (int e = 0; e < 2; e++) {
                    int gn = cb + e;
                    if (gn >= Nrows) continue;
                    float v = acc[mi][ni][half * 2 + e];
                    if (bias) v += bias[gn];
                    if (relu) v = fmaxf(v, 0.0f);
                    crow[gn] = v;
                }
            }
        }
    }
}

// ---------------------------------------------------------------------------
// Prep: concat projection weights (fp32), biases, biaffine bias column
// ---------------------------------------------------------------------------
__global__ void prep_kernel(const float* __restrict__ Wap, const float* __restrict__ bap,
                            const float* __restrict__ Wop, const float* __restrict__ bop,
                            const float* __restrict__ Wap2, const float* __restrict__ bap2,
                            const float* __restrict__ Wop2, const float* __restrict__ bop2,
                            const float* __restrict__ Wbi)
{
    int i = blockIdx.x * blockDim.x + threadIdx.x;
    if (i < PROJN * REDUC) {
        int n = i / REDUC, k = i % REDUC;
        const float* src = (n < 150) ? Wap : (n < 300) ? Wop : (n < 450) ? Wap2 : Wop2;
        g_WprojF[i] = src[(n % 150) * REDUC + k];
    }
    if (i < PROJN) {
        const float* sb = (i < 150) ? bap : (i < 300) ? bop : (i < 450) ? bap2 : bop2;
        g_bproj[i] = sb[i % 150];
        g_bbi[i]   = Wbi[i * 151 + 150];
    }
}

// ---------------------------------------------------------------------------
// Split fp32 -> [hi|lo] bf16 rows (grid.x = row)
// ---------------------------------------------------------------------------
__global__ void conv_split(const float* __restrict__ src, int sld, int soff,
                           __nv_bfloat16* __restrict__ dst, int Kp, int K)
{
    long r = blockIdx.x;
    const float* s = src + r * (long)sld + soff;
    __nv_bfloat16* d = dst + r * (long)(2 * Kp);
    for (int k = threadIdx.x; k < Kp; k += blockDim.x) {
        float v = (k < K) ? s[k] : 0.0f;
        __nv_bfloat16 hi = __float2bfloat16(v);
        float lo = v - __bfloat162float(hi);
        d[k]      = hi;
        d[Kp + k] = __float2bfloat16(lo);
    }
}

// ---------------------------------------------------------------------------
// Pool subwords + POS embed, writing split-bf16 h directly [m, 2*KP_H]
// ---------------------------------------------------------------------------
__global__ void pool_embed_bf(const float* __restrict__ bert,
                              const int* __restrict__ positions,
                              const int* __restrict__ postag,
                              const float* __restrict__ embed)
{
    int m = blockIdx.x;
    int b = m / L_;
    __shared__ int s_start, s_end, s_tag;
    if (threadIdx.x == 0) {
        s_start = positions[m * 2 + 0];
        s_end   = positions[m * 2 + 1];
        s_tag   = postag[m];
    }
    __syncthreads();
    const int start = s_start, end = s_end, tag = s_tag;
    const float inv = 1.0f / (float)(end - start + 1);
    const float* bb = bert + (long)b * S_ * D_;
    __nv_bfloat16* hrow = g_hbf + (long)m * 2 * KP_H;
    for (int f = threadIdx.x; f < KP_H; f += blockDim.x) {
        float v = 0.0f;
        if (f < POSD) {
            v = embed[tag * POSD + f];
        } else if (f < FEAT) {
            int d = f - POSD;
            float s = 0.0f;
            for (int si = start; si <= end; si++) s += bb[(long)si * D_ + d];
            v = s * inv;
        }
        __nv_bfloat16 hi = __float2bfloat16(v);
        float lo = v - __bfloat162float(hi);
        hrow[f]        = hi;
        hrow[KP_H + f] = __float2bfloat16(lo);
    }
}

// ---------------------------------------------------------------------------
// Tag heads (fp32, tiny)
// ---------------------------------------------------------------------------
__global__ void tag_kernel(const float* __restrict__ Wap, const float* __restrict__ bap,
                           const float* __restrict__ Wop, const float* __restrict__ bop,
                           float* __restrict__ out)
{
    int i = blockIdx.x * blockDim.x + threadIdx.x;
    if (i >= M_ * 2 * TAGS) return;
    int m = i / (2 * TAGS);
    int r = i % (2 * TAGS);
    int t = r % TAGS;
    bool is_op = (r >= TAGS);
    const float* a = g_proj + (long)m * PROJN + (is_op ? 150 : 0);
    const float* w = (is_op ? Wop : Wap) + t * HID;
    float s = (is_op ? bop : bap)[t];
#pragma unroll 5
    for (int k = 0; k < HID; k++) s += a[k] * w[k];
    out[(is_op ? (long)M_ * TAGS : 0l) + (long)m * TAGS + t] = s;
}

// ---------------------------------------------------------------------------
// kernel_launch
// ---------------------------------------------------------------------------
template <typename T_>
static T_* sym_addr(const void* symbol) {
    void* p = nullptr;
    cudaGetSymbolAddress(&p, symbol);
    return (T_*)p;
}

extern "C" void kernel_launch(void* const* d_in, const int* in_sizes, int n_in,
                              void* d_out, int out_size)
{
    const float* bert      = (const float*)d_in[0];
    const int*   positions = (const int*)  d_in[1];
    const int*   postag    = (const int*)  d_in[2];
    const float* embed     = (const float*)d_in[3];
    const float* W_reduc   = (const float*)d_in[4];
    const float* b_reduc   = (const float*)d_in[5];
    const float* W_ap      = (const float*)d_in[6];
    const float* b_ap      = (const float*)d_in[7];
    const float* W_op      = (const float*)d_in[8];
    const float* b_op      = (const float*)d_in[9];
    const float* W_ap2     = (const float*)d_in[10];
    const float* b_ap2     = (const float*)d_in[11];
    const float* W_op2     = (const float*)d_in[12];
    const float* b_op2     = (const float*)d_in[13];
    const float* W_aptag   = (const float*)d_in[14];
    const float* b_aptag   = (const float*)d_in[15];
    const float* W_optag   = (const float*)d_in[16];
    const float* b_optag   = (const float*)d_in[17];
    const float* W_bi      = (const float*)d_in[18];
    float* out = (float*)d_out;

    __nv_bfloat16* p_hbf      = sym_addr<__nv_bfloat16>(g_hbf);
    __nv_bfloat16* p_Wr_bf    = sym_addr<__nv_bfloat16>(g_Wr_bf);
    float*         p_reduc    = sym_addr<float>(g_reduc);
    __nv_bfloat16* p_reduc_bf = sym_addr<__nv_bfloat16>(g_reduc_bf);
    float*         p_WprojF   = sym_addr<float>(g_WprojF);
    __nv_bfloat16* p_Wp_bf    = sym_addr<__nv_bfloat16>(g_Wp_bf);
    float*         p_bproj    = sym_addr<float>(g_bproj);
    float*         p_bbi      = sym_addr<float>(g_bbi);
    float*         p_proj     = sym_addr<float>(g_proj);
    __nv_bfloat16* p_apn_bf   = sym_addr<__nv_bfloat16>(g_apn_bf);
    __nv_bfloat16* p_opn_bf   = sym_addr<__nv_bfloat16>(g_opn_bf);
    __nv_bfloat16* p_Wbi_bf   = sym_addr<__nv_bfloat16>(g_Wbi_bf);
    float*         p_affine   = sym_addr<float>(g_affine);
    __nv_bfloat16* p_aff_bf   = sym_addr<__nv_bfloat16>(g_aff_bf);

    cudaFuncSetAttribute(gemm_mma, cudaFuncAttributeMaxDynamicSharedMemorySize, SMEM_BYTES);

    // 1. weight prep + conversions
    prep_kernel<<<(PROJN * REDUC + 255) / 256, 256>>>(
        W_ap, b_ap, W_op, b_op, W_ap2, b_ap2, W_op2, b_op2, W_bi);
    conv_split<<<REDUC, 128>>>(W_reduc, FEAT, 0, p_Wr_bf, KP_H, FEAT);
    conv_split<<<PROJN, 128>>>(p_WprojF, REDUC, 0, p_Wp_bf, KP_R, REDUC);
    conv_split<<<PROJN, 128>>>(W_bi, 151, 0, p_Wbi_bf, KP_N, HID);

    // 2. pool + embed -> split-bf16 h
    pool_embed_bf<<<M_, 256>>>(bert, positions, postag, embed);

    // 3. reduc = h @ W_reduc^T + b    [25600, 400], T=13
    gemm_mma<<<dim3((REDUC + 127) / 128, M_ / 128, 1), 256, SMEM_BYTES>>>(
        p_hbf, 2 * KP_H, 0, M_, p_Wr_bf, 2 * KP_H, 0, REDUC,
        b_reduc, p_reduc, REDUC, 0, KP_H / 64, 0);
    conv_split<<<M_, 128>>>(p_reduc, REDUC, 0, p_reduc_bf, KP_R, REDUC);

    // 4. fused projections + relu -> proj [25600, 600], T=7
    gemm_mma<<<dim3((PROJN + 127) / 128, M_ / 128, 1), 256, SMEM_BYTES>>>(
        p_reduc_bf, 2 * KP_R, 0, M_, p_Wp_bf, 2 * KP_R, 0, PROJN,
        p_bproj, p_proj, PROJN, 0, KP_R / 64, 1);
    conv_split<<<M_, 128>>>(p_proj, PROJN, 300, p_apn_bf, KP_N, HID);
    conv_split<<<M_, 128>>>(p_proj, PROJN, 450, p_opn_bf, KP_N, HID);

    // 5. affine = ap_node @ W_bi[:, :150]^T + bbi  [25600, 600], T=3
    gemm_mma<<<dim3((PROJN + 127) / 128, M_ / 128, 1), 256, SMEM_BYTES>>>(
        p_apn_bf, 2 * KP_N, 0, M_, p_Wbi_bf, 2 * KP_N, 0, PROJN,
        p_bbi, p_affine, PROJN, 0, KP_N / 64, 0);
    // affine fp32 [25600,600] flat == [102400,150] rows -> split-bf16
    conv_split<<<B_ * 800, 128>>>(p_affine, HID, 0, p_aff_bf, KP_N, HID);

    // 6. tag heads -> out[0 : 256000]
    tag_kernel<<<(M_ * 10 + 255) / 256, 256>>>(W_aptag, b_aptag, W_optag, b_optag, out);

    // 7. triplet per batch: C[l2, l1*4+p] = op_node[l2,:] . affine[l1*4+p,:]
    gemm_mma<<<dim3((800 + 127) / 128, (L_ + 127) / 128, B_), 256, SMEM_BYTES>>>(
        p_opn_bf, 2 * KP_N, (long)L_ * 2 * KP_N, L_,
        p_aff_bf, 2 * KP_N, (long)800 * 2 * KP_N, 800,
        nullptr,
        out + 2l * M_ * TAGS, 800, 160000l,
        KP_N / 64, 0);
}